// round 14
// baseline (speedup 1.0000x reference)
#include <cuda_runtime.h>
#include <cuda_bf16.h>
#include <cstdint>

// DEQ via warp-level bf16 HMMA, c folded into the GEMM (K = 144, 9 k-tiles):
//   z~ = [z(128) | x_hi(4) | x_hi(4) | x_lo(4) | 1 | 1 | 0 0]
//   W~ = [B      | Aw_hi   | Aw_lo   | Aw_hi   | b_hi | b_lo | 0 0]
// => pre-act = z.B^T + x_hi.Aw + x_lo.Aw_hi + bias  (error ~1e-5; the R13
// single-Aw version lost 5e-4 to Aw's bf16 quantization).
// 3 tanh applications; y = z3.h + hb fused into the last GEMM iteration.
// R14: + dynamic band scheduling via global atomic counter (reset by a tiny
// pre-kernel) to remove the 3.46->4 bands/warp static-stride imbalance.
// 512 threads (16 warps, 4/SMSP, 128-reg cap), z in per-warp SMEM,
// independent 16-row bands, __syncwarp only, persistent grid.

#define THREADS 512
#define NWARPS  16
#define LDW     304        // bytes per W~/Z row (144 bf16 = 288 B + 16 pad)
#define ZSLICE  (16 * LDW) // 4864 B per warp
#define SM_W    0          // 128 * 304 = 38912 B
#define SM_Z    38912      // 16 * 4864 = 77824 B
#define SM_H    116736     // 512 B
#define SM_TOTAL 117248

__device__ unsigned int g_band_counter;

__global__ void reset_counter_kernel() { g_band_counter = 0u; }

__device__ __forceinline__ float tanh_exact(float v) {
    float e = __expf(2.0f * v);
    return 1.0f - __fdividef(2.0f, e + 1.0f);
}
__device__ __forceinline__ float tanh_apx(float v) {
    float r; asm("tanh.approx.f32 %0, %1;" : "=f"(r) : "f"(v)); return r;
}
// pack {lo, hi} floats into bf16x2 (lo -> low 16 bits = lower column)
__device__ __forceinline__ uint32_t packlh(float lo, float hi) {
    uint32_t r;
    asm("cvt.rn.satfinite.bf16x2.f32 %0, %1, %2;" : "=r"(r) : "f"(hi), "f"(lo));
    return r;
}
__device__ __forceinline__ void mma16816(float* d, const uint32_t* a,
                                         uint32_t b0, uint32_t b1) {
    asm volatile(
        "mma.sync.aligned.m16n8k16.row.col.f32.bf16.bf16.f32 "
        "{%0,%1,%2,%3}, {%4,%5,%6,%7}, {%8,%9}, {%0,%1,%2,%3};"
        : "+f"(d[0]), "+f"(d[1]), "+f"(d[2]), "+f"(d[3])
        : "r"(a[0]), "r"(a[1]), "r"(a[2]), "r"(a[3]), "r"(b0), "r"(b1));
}
__device__ __forceinline__ void ldsm4(uint32_t* r, uint32_t addr) {
    asm volatile("ldmatrix.sync.aligned.m8n8.x4.shared.b16 {%0,%1,%2,%3}, [%4];"
                 : "=r"(r[0]), "=r"(r[1]), "=r"(r[2]), "=r"(r[3]) : "r"(addr));
}
__device__ __forceinline__ void ldsm2(uint32_t* r, uint32_t addr) {
    asm volatile("ldmatrix.sync.aligned.m8n8.x2.shared.b16 {%0,%1}, [%2];"
                 : "=r"(r[0]), "=r"(r[1]) : "r"(addr));
}
__device__ __forceinline__ void sts32(uint32_t addr, uint32_t v) {
    asm volatile("st.shared.b32 [%0], %1;" :: "r"(addr), "r"(v) : "memory");
}
__device__ __forceinline__ void sts128(uint32_t addr, uint32_t a, uint32_t b,
                                       uint32_t c, uint32_t d) {
    asm volatile("st.shared.v4.b32 [%0], {%1,%2,%3,%4};"
                 :: "r"(addr), "r"(a), "r"(b), "r"(c), "r"(d) : "memory");
}

// One GEMM iteration over the extended K (9 k-tiles).
// FIRST: z=0, only kt8 (the c columns) contributes.
// LAST:  fuse y = z.h instead of storing z_next.
template<bool FIRST, bool LAST>
__device__ __forceinline__ void gemm_iter(
    uint32_t bb, uint32_t za, uint32_t zs, const float2* h2,
    float& y0, float& y1, int qc)
{
    uint32_t A[9][4];
    if (!FIRST) {
        #pragma unroll
        for (int kt = 0; kt < 8; ++kt) ldsm4(A[kt], za + kt * 32);
    }
    ldsm4(A[8], za + 256);   // x_hi/x_hi/x_lo/ones columns (bytes 256-287)

    #pragma unroll
    for (int ntp = 0; ntp < 8; ++ntp) {
        const uint32_t b0a = bb + (uint32_t)(2 * ntp)     * (8 * LDW);
        const uint32_t b1a = bb + (uint32_t)(2 * ntp + 1) * (8 * LDW);
        float acc0[4] = {0.f, 0.f, 0.f, 0.f};
        float acc1[4] = {0.f, 0.f, 0.f, 0.f};
        if (!FIRST) {
            #pragma unroll
            for (int l = 0; l < 4; ++l) {
                uint32_t b0[4], b1[4];
                ldsm4(b0, b0a + l * 64);
                ldsm4(b1, b1a + l * 64);
                mma16816(acc0, A[2 * l],     b0[0], b0[1]);
                mma16816(acc0, A[2 * l + 1], b0[2], b0[3]);
                mma16816(acc1, A[2 * l],     b1[0], b1[1]);
                mma16816(acc1, A[2 * l + 1], b1[2], b1[3]);
            }
        }
        {   // kt8: c contribution (Aw hi/lo + bias hi/lo columns)
            uint32_t c0[2], c1[2];
            ldsm2(c0, b0a + 256);
            ldsm2(c1, b1a + 256);
            mma16816(acc0, A[8], c0[0], c0[1]);
            mma16816(acc1, A[8], c1[0], c1[1]);
        }
        #pragma unroll
        for (int h = 0; h < 2; ++h) {
            const int nt = 2 * ntp + h;
            const float* acc = h ? acc1 : acc0;
            if (LAST) {
                float2 hv = h2[4 * nt + qc];
                y0 += hv.x * tanh_exact(acc[0]) + hv.y * tanh_exact(acc[1]);
                y1 += hv.x * tanh_exact(acc[2]) + hv.y * tanh_exact(acc[3]);
            } else {
                uint32_t off = (uint32_t)(nt * 8 + 2 * qc) * 2;
                sts32(zs + off,           packlh(tanh_apx(acc[0]), tanh_apx(acc[1])));
                sts32(zs + 8 * LDW + off, packlh(tanh_apx(acc[2]), tanh_apx(acc[3])));
            }
        }
    }
}

__global__ void __launch_bounds__(THREADS, 1)
deq_mma_kernel(const float* __restrict__ x,
               const float* __restrict__ Aw,
               const float* __restrict__ Ab,
               const float* __restrict__ Bw,
               const float* __restrict__ Bb,
               const float* __restrict__ hw,
               const float* __restrict__ hb,
               float* __restrict__ out,
               int nbands)
{
    extern __shared__ char smem[];
    const int tid = threadIdx.x;

    // ---- one-time staging: W~ (bf16, padded rows) and h ----
    for (int idx = tid; idx < 128 * 144; idx += THREADS) {
        int n = idx / 144, k = idx % 144;
        float v;
        if (k < 128) {
            v = Bw[n * 128 + k];
        } else if (k < 132) {            // Aw_hi (bf16 store rounds)
            v = Aw[n * 4 + (k - 128)];
        } else if (k < 136) {            // Aw_lo
            float a = Aw[n * 4 + (k - 132)];
            v = a - __bfloat162float(__float2bfloat16(a));
        } else if (k < 140) {            // Aw_hi again (pairs with x_lo)
            v = Aw[n * 4 + (k - 136)];
        } else if (k == 140) {           // bias_hi
            v = Ab[n] + Bb[n];
        } else if (k == 141) {           // bias_lo
            float b = Ab[n] + Bb[n];
            v = b - __bfloat162float(__float2bfloat16(b));
        } else {
            v = 0.0f;
        }
        *(__nv_bfloat16*)(smem + SM_W + n * LDW + k * 2) = __float2bfloat16(v);
    }
    if (tid < 128) ((float*)(smem + SM_H))[tid] = hw[tid];
    __syncthreads();

    // ---- per-thread constants ----
    const int lane = tid & 31, wid = tid >> 5;
    const int qr = lane >> 2, qc = lane & 3;
    const float2* h2  = (const float2*)(smem + SM_H);
    const uint32_t sb = (uint32_t)__cvta_generic_to_shared(smem);
    const uint32_t bb = sb + SM_W + (uint32_t)(lane & 7) * LDW + (uint32_t)(lane >> 3) * 16;
    const uint32_t zb = sb + SM_Z + (uint32_t)wid * ZSLICE;
    const uint32_t za = zb + (uint32_t)(lane & 15) * LDW + (uint32_t)(lane >> 4) * 16;
    const uint32_t zs = zb + (uint32_t)qr * LDW;
    const float hb0 = hb[0];

    const int cr = lane >> 1;                         // prologue: lane pair per row
    const uint32_t zrow = zb + (uint32_t)cr * LDW;

    for (;;) {
        // ---- grab next band from the global queue ----
        unsigned int band = 0u;
        if (lane == 0) band = atomicAdd(&g_band_counter, 1u);
        band = __shfl_sync(0xffffffffu, band, 0);
        if (band >= (unsigned int)nbands) break;
        const int row0 = (int)band * 16;

        // ---- prologue: write x_hi/x_hi/x_lo/ones columns (bytes 256-287) ----
        __syncwarp();   // previous band's ldsm reads of Z are done
        {
            float4 xv = ((const float4*)x)[row0 + cr];
            float hx = __bfloat162float(__float2bfloat16(xv.x));
            float hy = __bfloat162float(__float2bfloat16(xv.y));
            float hz = __bfloat162float(__float2bfloat16(xv.z));
            float hw_ = __bfloat162float(__float2bfloat16(xv.w));
            if ((lane & 1) == 0) {
                uint32_t p0 = packlh(xv.x, xv.y);   // rounds to x_hi
                uint32_t p1 = packlh(xv.z, xv.w);
                sts128(zrow + 256, p0, p1, p0, p1);
            } else {
                sts128(zrow + 272,
                       packlh(xv.x - hx, xv.y - hy),
                       packlh(xv.z - hz, xv.w - hw_),
                       packlh(1.0f, 1.0f), 0u);
            }
        }
        __syncwarp();

        // ---- 3 applications: z1 (kt8 only), z2, z3 + y ----
        float y0 = 0.f, y1 = 0.f;
        gemm_iter<true,  false>(bb, za, zs, h2, y0, y1, qc);
        __syncwarp();
        gemm_iter<false, false>(bb, za, zs, h2, y0, y1, qc);
        __syncwarp();
        gemm_iter<false, true >(bb, za, zs, h2, y0, y1, qc);

        // ---- reduce y across the 4 lanes sharing a row, write out ----
        y0 += __shfl_xor_sync(0xffffffffu, y0, 1);
        y0 += __shfl_xor_sync(0xffffffffu, y0, 2);
        y1 += __shfl_xor_sync(0xffffffffu, y1, 1);
        y1 += __shfl_xor_sync(0xffffffffu, y1, 2);
        if (qc == 0) {
            out[row0 + qr]     = y0 + hb0;
            out[row0 + qr + 8] = y1 + hb0;
        }
    }
}

extern "C" void kernel_launch(void* const* d_in, const int* in_sizes, int n_in,
                              void* d_out, int out_size) {
    const float* x  = (const float*)d_in[0];
    const float* Aw = (const float*)d_in[1];
    const float* Ab = (const float*)d_in[2];
    const float* Bw = (const float*)d_in[3];
    const float* Bb = (const float*)d_in[4];
    const float* hw = (const float*)d_in[5];
    const float* hb = (const float*)d_in[6];
    float* out = (float*)d_out;

    int batch  = in_sizes[0] / 4;   // x is [batch, 4]
    int nbands = batch / 16;        // 8192
    int grid   = 148;               // persistent: one CTA per SM

    reset_counter_kernel<<<1, 1>>>();
    cudaFuncSetAttribute(deq_mma_kernel,
                         cudaFuncAttributeMaxDynamicSharedMemorySize,
                         SM_TOTAL);
    deq_mma_kernel<<<grid, THREADS, SM_TOTAL>>>(x, Aw, Ab, Bw, Bb, hw, hb, out, nbands);
}

// round 15
// speedup vs baseline: 1.0271x; 1.0271x over previous
#include <cuda_runtime.h>
#include <cuda_bf16.h>
#include <cstdint>

// DEQ via warp-level bf16 HMMA, c folded into the GEMM (K = 144, 9 k-tiles):
//   z~ = [z(128) | x_hi(4) | x_hi(4) | x_lo(4) | 1 | 1 | 0 0]
//   W~ = [B      | Aw_hi   | Aw_lo   | Aw_hi   | b_hi | b_lo | 0 0]
// => pre-act = z.B^T + x_hi.Aw + x_lo.Aw_hi + bias  (c-path error ~1e-5).
// 3 tanh applications; y = z3.h + hb fused into the last GEMM iteration.
// R15: per-CTA SMEM work counter (16 warps drain the CTA's static band range)
// replaces R14's global counter + reset kernel -> single graph node, same
// balance. 512 threads (16 warps, 4/SMSP, 128-reg cap), z in per-warp SMEM,
// independent 16-row bands, __syncwarp only, persistent grid.

#define THREADS 512
#define NWARPS  16
#define LDW     304        // bytes per W~/Z row (144 bf16 = 288 B + 16 pad)
#define ZSLICE  (16 * LDW) // 4864 B per warp
#define SM_W    0          // 128 * 304 = 38912 B
#define SM_Z    38912      // 16 * 4864 = 77824 B
#define SM_H    116736     // 512 B
#define SM_CNT  117248     // 4 B work counter
#define SM_TOTAL 117280

__device__ __forceinline__ float tanh_exact(float v) {
    float e = __expf(2.0f * v);
    return 1.0f - __fdividef(2.0f, e + 1.0f);
}
__device__ __forceinline__ float tanh_apx(float v) {
    float r; asm("tanh.approx.f32 %0, %1;" : "=f"(r) : "f"(v)); return r;
}
// pack {lo, hi} floats into bf16x2 (lo -> low 16 bits = lower column)
__device__ __forceinline__ uint32_t packlh(float lo, float hi) {
    uint32_t r;
    asm("cvt.rn.satfinite.bf16x2.f32 %0, %1, %2;" : "=r"(r) : "f"(hi), "f"(lo));
    return r;
}
__device__ __forceinline__ void mma16816(float* d, const uint32_t* a,
                                         uint32_t b0, uint32_t b1) {
    asm volatile(
        "mma.sync.aligned.m16n8k16.row.col.f32.bf16.bf16.f32 "
        "{%0,%1,%2,%3}, {%4,%5,%6,%7}, {%8,%9}, {%0,%1,%2,%3};"
        : "+f"(d[0]), "+f"(d[1]), "+f"(d[2]), "+f"(d[3])
        : "r"(a[0]), "r"(a[1]), "r"(a[2]), "r"(a[3]), "r"(b0), "r"(b1));
}
__device__ __forceinline__ void ldsm4(uint32_t* r, uint32_t addr) {
    asm volatile("ldmatrix.sync.aligned.m8n8.x4.shared.b16 {%0,%1,%2,%3}, [%4];"
                 : "=r"(r[0]), "=r"(r[1]), "=r"(r[2]), "=r"(r[3]) : "r"(addr));
}
__device__ __forceinline__ void ldsm2(uint32_t* r, uint32_t addr) {
    asm volatile("ldmatrix.sync.aligned.m8n8.x2.shared.b16 {%0,%1}, [%2];"
                 : "=r"(r[0]), "=r"(r[1]) : "r"(addr));
}
__device__ __forceinline__ void sts32(uint32_t addr, uint32_t v) {
    asm volatile("st.shared.b32 [%0], %1;" :: "r"(addr), "r"(v) : "memory");
}
__device__ __forceinline__ void sts128(uint32_t addr, uint32_t a, uint32_t b,
                                       uint32_t c, uint32_t d) {
    asm volatile("st.shared.v4.b32 [%0], {%1,%2,%3,%4};"
                 :: "r"(addr), "r"(a), "r"(b), "r"(c), "r"(d) : "memory");
}

// One GEMM iteration over the extended K (9 k-tiles).
// FIRST: z=0, only kt8 (the c columns) contributes.
// LAST:  fuse y = z.h instead of storing z_next.
template<bool FIRST, bool LAST>
__device__ __forceinline__ void gemm_iter(
    uint32_t bb, uint32_t za, uint32_t zs, const float2* h2,
    float& y0, float& y1, int qc)
{
    uint32_t A[9][4];
    if (!FIRST) {
        #pragma unroll
        for (int kt = 0; kt < 8; ++kt) ldsm4(A[kt], za + kt * 32);
    }
    ldsm4(A[8], za + 256);   // x_hi/x_hi/x_lo/ones columns (bytes 256-287)

    #pragma unroll
    for (int ntp = 0; ntp < 8; ++ntp) {
        const uint32_t b0a = bb + (uint32_t)(2 * ntp)     * (8 * LDW);
        const uint32_t b1a = bb + (uint32_t)(2 * ntp + 1) * (8 * LDW);
        float acc0[4] = {0.f, 0.f, 0.f, 0.f};
        float acc1[4] = {0.f, 0.f, 0.f, 0.f};
        if (!FIRST) {
            #pragma unroll
            for (int l = 0; l < 4; ++l) {
                uint32_t b0[4], b1[4];
                ldsm4(b0, b0a + l * 64);
                ldsm4(b1, b1a + l * 64);
                mma16816(acc0, A[2 * l],     b0[0], b0[1]);
                mma16816(acc0, A[2 * l + 1], b0[2], b0[3]);
                mma16816(acc1, A[2 * l],     b1[0], b1[1]);
                mma16816(acc1, A[2 * l + 1], b1[2], b1[3]);
            }
        }
        {   // kt8: c contribution (Aw hi/lo + bias hi/lo columns)
            uint32_t c0[2], c1[2];
            ldsm2(c0, b0a + 256);
            ldsm2(c1, b1a + 256);
            mma16816(acc0, A[8], c0[0], c0[1]);
            mma16816(acc1, A[8], c1[0], c1[1]);
        }
        #pragma unroll
        for (int h = 0; h < 2; ++h) {
            const int nt = 2 * ntp + h;
            const float* acc = h ? acc1 : acc0;
            if (LAST) {
                float2 hv = h2[4 * nt + qc];
                y0 += hv.x * tanh_exact(acc[0]) + hv.y * tanh_exact(acc[1]);
                y1 += hv.x * tanh_exact(acc[2]) + hv.y * tanh_exact(acc[3]);
            } else {
                uint32_t off = (uint32_t)(nt * 8 + 2 * qc) * 2;
                sts32(zs + off,           packlh(tanh_apx(acc[0]), tanh_apx(acc[1])));
                sts32(zs + 8 * LDW + off, packlh(tanh_apx(acc[2]), tanh_apx(acc[3])));
            }
        }
    }
}

__global__ void __launch_bounds__(THREADS, 1)
deq_mma_kernel(const float* __restrict__ x,
               const float* __restrict__ Aw,
               const float* __restrict__ Ab,
               const float* __restrict__ Bw,
               const float* __restrict__ Bb,
               const float* __restrict__ hw,
               const float* __restrict__ hb,
               float* __restrict__ out,
               int nbands)
{
    extern __shared__ char smem[];
    const int tid = threadIdx.x;

    // this CTA's static band range (covers all bands, disjoint, ~balanced)
    const unsigned int cta_lo = (unsigned int)(((long long)blockIdx.x * nbands) / gridDim.x);
    const unsigned int cta_hi = (unsigned int)(((long long)(blockIdx.x + 1) * nbands) / gridDim.x);
    unsigned int* cnt = (unsigned int*)(smem + SM_CNT);
    if (tid == 0) *cnt = cta_lo;

    // ---- one-time staging: W~ (bf16, padded rows) and h ----
    for (int idx = tid; idx < 128 * 144; idx += THREADS) {
        int n = idx / 144, k = idx % 144;
        float v;
        if (k < 128) {
            v = Bw[n * 128 + k];
        } else if (k < 132) {            // Aw_hi (bf16 store rounds)
            v = Aw[n * 4 + (k - 128)];
        } else if (k < 136) {            // Aw_lo
            float a = Aw[n * 4 + (k - 132)];
            v = a - __bfloat162float(__float2bfloat16(a));
        } else if (k < 140) {            // Aw_hi again (pairs with x_lo)
            v = Aw[n * 4 + (k - 136)];
        } else if (k == 140) {           // bias_hi
            v = Ab[n] + Bb[n];
        } else if (k == 141) {           // bias_lo
            float b = Ab[n] + Bb[n];
            v = b - __bfloat162float(__float2bfloat16(b));
        } else {
            v = 0.0f;
        }
        *(__nv_bfloat16*)(smem + SM_W + n * LDW + k * 2) = __float2bfloat16(v);
    }
    if (tid < 128) ((float*)(smem + SM_H))[tid] = hw[tid];
    __syncthreads();

    // ---- per-thread constants ----
    const int lane = tid & 31, wid = tid >> 5;
    const int qr = lane >> 2, qc = lane & 3;
    const float2* h2  = (const float2*)(smem + SM_H);
    const uint32_t sb = (uint32_t)__cvta_generic_to_shared(smem);
    const uint32_t bb = sb + SM_W + (uint32_t)(lane & 7) * LDW + (uint32_t)(lane >> 3) * 16;
    const uint32_t zb = sb + SM_Z + (uint32_t)wid * ZSLICE;
    const uint32_t za = zb + (uint32_t)(lane & 15) * LDW + (uint32_t)(lane >> 4) * 16;
    const uint32_t zs = zb + (uint32_t)qr * LDW;
    const float hb0 = hb[0];

    const int cr = lane >> 1;                         // prologue: lane pair per row
    const uint32_t zrow = zb + (uint32_t)cr * LDW;

    for (;;) {
        // ---- grab next band from the CTA-local queue (SMEM atomic) ----
        unsigned int band = 0u;
        if (lane == 0) band = atomicAdd(cnt, 1u);
        band = __shfl_sync(0xffffffffu, band, 0);
        if (band >= cta_hi) break;
        const int row0 = (int)band * 16;

        // ---- prologue: write x_hi/x_hi/x_lo/ones columns (bytes 256-287) ----
        __syncwarp();   // previous band's ldsm reads of Z are done
        {
            float4 xv = ((const float4*)x)[row0 + cr];
            float hx = __bfloat162float(__float2bfloat16(xv.x));
            float hy = __bfloat162float(__float2bfloat16(xv.y));
            float hz = __bfloat162float(__float2bfloat16(xv.z));
            float hw_ = __bfloat162float(__float2bfloat16(xv.w));
            if ((lane & 1) == 0) {
                uint32_t p0 = packlh(xv.x, xv.y);   // rounds to x_hi
                uint32_t p1 = packlh(xv.z, xv.w);
                sts128(zrow + 256, p0, p1, p0, p1);
            } else {
                sts128(zrow + 272,
                       packlh(xv.x - hx, xv.y - hy),
                       packlh(xv.z - hz, xv.w - hw_),
                       packlh(1.0f, 1.0f), 0u);
            }
        }
        __syncwarp();

        // ---- 3 applications: z1 (kt8 only), z2, z3 + y ----
        float y0 = 0.f, y1 = 0.f;
        gemm_iter<true,  false>(bb, za, zs, h2, y0, y1, qc);
        __syncwarp();
        gemm_iter<false, false>(bb, za, zs, h2, y0, y1, qc);
        __syncwarp();
        gemm_iter<false, true >(bb, za, zs, h2, y0, y1, qc);

        // ---- reduce y across the 4 lanes sharing a row, write out ----
        y0 += __shfl_xor_sync(0xffffffffu, y0, 1);
        y0 += __shfl_xor_sync(0xffffffffu, y0, 2);
        y1 += __shfl_xor_sync(0xffffffffu, y1, 1);
        y1 += __shfl_xor_sync(0xffffffffu, y1, 2);
        if (qc == 0) {
            out[row0 + qr]     = y0 + hb0;
            out[row0 + qr + 8] = y1 + hb0;
        }
    }
}

extern "C" void kernel_launch(void* const* d_in, const int* in_sizes, int n_in,
                              void* d_out, int out_size) {
    const float* x  = (const float*)d_in[0];
    const float* Aw = (const float*)d_in[1];
    const float* Ab = (const float*)d_in[2];
    const float* Bw = (const float*)d_in[3];
    const float* Bb = (const float*)d_in[4];
    const float* hw = (const float*)d_in[5];
    const float* hb = (const float*)d_in[6];
    float* out = (float*)d_out;

    int batch  = in_sizes[0] / 4;   // x is [batch, 4]
    int nbands = batch / 16;        // 8192
    int grid   = 148;               // persistent: one CTA per SM

    cudaFuncSetAttribute(deq_mma_kernel,
                         cudaFuncAttributeMaxDynamicSharedMemorySize,
                         SM_TOTAL);
    deq_mma_kernel<<<grid, THREADS, SM_TOTAL>>>(x, Aw, Ab, Bw, Bb, hw, hb, out, nbands);
}

// round 16
// speedup vs baseline: 1.1426x; 1.1125x over previous
#include <cuda_runtime.h>
#include <cuda_bf16.h>
#include <cstdint>

// DEQ via warp-level bf16 HMMA, c folded into the GEMM (K = 144, 9 k-tiles):
//   z~ = [z(128) | x_hi(4) | x_hi(4) | x_lo(4) | 1 | 1 | 0 0]
//   W~ = [B      | Aw_hi   | Aw_lo   | Aw_hi   | b_hi | b_lo | 0 0]
// 3 tanh applications; y = z3.h + hb fused into the last GEMM iteration.
// R16: 640 threads (20 warps, 5/SMSP, 102-reg cap; audited live set ~80);
// c-column ldsm2 pair merged into one lane-remapped ldsm4; A[8] (x/ones
// fragment, constant per band) hoisted out of the per-iteration reload.
// Per-CTA SMEM work counter; z in per-warp SMEM; __syncwarp only.

#define THREADS 640
#define NWARPS  20
#define LDW     304        // bytes per W~/Z row (144 bf16 = 288 B + 16 pad)
#define ZSLICE  (16 * LDW) // 4864 B per warp
#define SM_W    0          // 128 * 304 = 38912 B
#define SM_Z    38912      // 20 * 4864 = 97280 B
#define SM_H    136192     // 512 B
#define SM_CNT  136704     // 4 B work counter
#define SM_TOTAL 136736

__device__ __forceinline__ float tanh_exact(float v) {
    float e = __expf(2.0f * v);
    return 1.0f - __fdividef(2.0f, e + 1.0f);
}
__device__ __forceinline__ float tanh_apx(float v) {
    float r; asm("tanh.approx.f32 %0, %1;" : "=f"(r) : "f"(v)); return r;
}
// pack {lo, hi} floats into bf16x2 (lo -> low 16 bits = lower column)
__device__ __forceinline__ uint32_t packlh(float lo, float hi) {
    uint32_t r;
    asm("cvt.rn.satfinite.bf16x2.f32 %0, %1, %2;" : "=r"(r) : "f"(hi), "f"(lo));
    return r;
}
__device__ __forceinline__ void mma16816(float* d, const uint32_t* a,
                                         uint32_t b0, uint32_t b1) {
    asm volatile(
        "mma.sync.aligned.m16n8k16.row.col.f32.bf16.bf16.f32 "
        "{%0,%1,%2,%3}, {%4,%5,%6,%7}, {%8,%9}, {%0,%1,%2,%3};"
        : "+f"(d[0]), "+f"(d[1]), "+f"(d[2]), "+f"(d[3])
        : "r"(a[0]), "r"(a[1]), "r"(a[2]), "r"(a[3]), "r"(b0), "r"(b1));
}
__device__ __forceinline__ void ldsm4(uint32_t* r, uint32_t addr) {
    asm volatile("ldmatrix.sync.aligned.m8n8.x4.shared.b16 {%0,%1,%2,%3}, [%4];"
                 : "=r"(r[0]), "=r"(r[1]), "=r"(r[2]), "=r"(r[3]) : "r"(addr));
}
__device__ __forceinline__ void sts32(uint32_t addr, uint32_t v) {
    asm volatile("st.shared.b32 [%0], %1;" :: "r"(addr), "r"(v) : "memory");
}
__device__ __forceinline__ void sts128(uint32_t addr, uint32_t a, uint32_t b,
                                       uint32_t c, uint32_t d) {
    asm volatile("st.shared.v4.b32 [%0], {%1,%2,%3,%4};"
                 :: "r"(addr), "r"(a), "r"(b), "r"(c), "r"(d) : "memory");
}

// One GEMM iteration over the extended K (9 k-tiles).
// FIRST: z=0, only the c columns contribute.  LAST: fuse y = z.h.
// A8 = constant x/ones fragment (hoisted, per band).
// ccb = lane-remapped base for the merged c-column ldsm4:
//   groups (lane>>3): {b0 k-lo, b0 k-hi, b1 k-lo, b1 k-hi}
template<bool FIRST, bool LAST>
__device__ __forceinline__ void gemm_iter(
    uint32_t bb, uint32_t ccb, uint32_t za, uint32_t zs, const float2* h2,
    const uint32_t A8[4], float& y0, float& y1, int qc)
{
    uint32_t A[8][4];
    if (!FIRST) {
        #pragma unroll
        for (int kt = 0; kt < 8; ++kt) ldsm4(A[kt], za + kt * 32);
    }

    #pragma unroll
    for (int ntp = 0; ntp < 8; ++ntp) {
        const uint32_t b0a = bb + (uint32_t)(2 * ntp)     * (8 * LDW);
        const uint32_t b1a = bb + (uint32_t)(2 * ntp + 1) * (8 * LDW);
        float acc0[4] = {0.f, 0.f, 0.f, 0.f};
        float acc1[4] = {0.f, 0.f, 0.f, 0.f};
        {   // c contribution: merged ldsm4 (b0 lo, b0 hi, b1 lo, b1 hi)
            uint32_t c[4];
            ldsm4(c, ccb + (uint32_t)ntp * (16 * LDW));
            mma16816(acc0, A8, c[0], c[1]);
            mma16816(acc1, A8, c[2], c[3]);
        }
        if (!FIRST) {
            #pragma unroll
            for (int l = 0; l < 4; ++l) {
                uint32_t b0[4], b1[4];
                ldsm4(b0, b0a + l * 64);
                ldsm4(b1, b1a + l * 64);
                mma16816(acc0, A[2 * l],     b0[0], b0[1]);
                mma16816(acc0, A[2 * l + 1], b0[2], b0[3]);
                mma16816(acc1, A[2 * l],     b1[0], b1[1]);
                mma16816(acc1, A[2 * l + 1], b1[2], b1[3]);
            }
        }
        #pragma unroll
        for (int h = 0; h < 2; ++h) {
            const int nt = 2 * ntp + h;
            const float* acc = h ? acc1 : acc0;
            if (LAST) {
                float2 hv = h2[4 * nt + qc];
                y0 += hv.x * tanh_exact(acc[0]) + hv.y * tanh_exact(acc[1]);
                y1 += hv.x * tanh_exact(acc[2]) + hv.y * tanh_exact(acc[3]);
            } else {
                uint32_t off = (uint32_t)(nt * 8 + 2 * qc) * 2;
                sts32(zs + off,           packlh(tanh_apx(acc[0]), tanh_apx(acc[1])));
                sts32(zs + 8 * LDW + off, packlh(tanh_apx(acc[2]), tanh_apx(acc[3])));
            }
        }
    }
}

__global__ void __launch_bounds__(THREADS, 1)
deq_mma_kernel(const float* __restrict__ x,
               const float* __restrict__ Aw,
               const float* __restrict__ Ab,
               const float* __restrict__ Bw,
               const float* __restrict__ Bb,
               const float* __restrict__ hw,
               const float* __restrict__ hb,
               float* __restrict__ out,
               int nbands)
{
    extern __shared__ char smem[];
    const int tid = threadIdx.x;

    // this CTA's static band range (covers all bands, disjoint, ~balanced)
    const unsigned int cta_lo = (unsigned int)(((long long)blockIdx.x * nbands) / gridDim.x);
    const unsigned int cta_hi = (unsigned int)(((long long)(blockIdx.x + 1) * nbands) / gridDim.x);
    unsigned int* cnt = (unsigned int*)(smem + SM_CNT);
    if (tid == 0) *cnt = cta_lo;

    // ---- one-time staging: W~ (bf16, padded rows) and h ----
    for (int idx = tid; idx < 128 * 144; idx += THREADS) {
        int n = idx / 144, k = idx % 144;
        float v;
        if (k < 128) {
            v = Bw[n * 128 + k];
        } else if (k < 132) {            // Aw_hi (bf16 store rounds)
            v = Aw[n * 4 + (k - 128)];
        } else if (k < 136) {            // Aw_lo
            float a = Aw[n * 4 + (k - 132)];
            v = a - __bfloat162float(__float2bfloat16(a));
        } else if (k < 140) {            // Aw_hi again (pairs with x_lo)
            v = Aw[n * 4 + (k - 136)];
        } else if (k == 140) {           // bias_hi
            v = Ab[n] + Bb[n];
        } else if (k == 141) {           // bias_lo
            float b = Ab[n] + Bb[n];
            v = b - __bfloat162float(__float2bfloat16(b));
        } else {
            v = 0.0f;
        }
        *(__nv_bfloat16*)(smem + SM_W + n * LDW + k * 2) = __float2bfloat16(v);
    }
    if (tid < 128) ((float*)(smem + SM_H))[tid] = hw[tid];
    __syncthreads();

    // ---- per-thread constants ----
    const int lane = tid & 31, wid = tid >> 5;
    const int qr = lane >> 2, qc = lane & 3;
    const float2* h2  = (const float2*)(smem + SM_H);
    const uint32_t sb = (uint32_t)__cvta_generic_to_shared(smem);
    const uint32_t bb = sb + SM_W + (uint32_t)(lane & 7) * LDW + (uint32_t)(lane >> 3) * 16;
    // merged c-column ldsm4 base: row = (lane&7) + ((lane>>4)&1)*8 (b0 vs b1),
    // k-group = ((lane>>3)&1)*16, at byte offset 256
    const uint32_t ccb = sb + SM_W
                       + ((uint32_t)(lane & 7) + (uint32_t)((lane >> 4) & 1) * 8) * LDW
                       + 256 + (uint32_t)((lane >> 3) & 1) * 16;
    const uint32_t zb = sb + SM_Z + (uint32_t)wid * ZSLICE;
    const uint32_t za = zb + (uint32_t)(lane & 15) * LDW + (uint32_t)(lane >> 4) * 16;
    const uint32_t zs = zb + (uint32_t)qr * LDW;
    const float hb0 = hb[0];

    const int cr = lane >> 1;                         // prologue: lane pair per row
    const uint32_t zrow = zb + (uint32_t)cr * LDW;

    for (;;) {
        // ---- grab next band from the CTA-local queue (SMEM atomic) ----
        unsigned int band = 0u;
        if (lane == 0) band = atomicAdd(cnt, 1u);
        band = __shfl_sync(0xffffffffu, band, 0);
        if (band >= cta_hi) break;
        const int row0 = (int)band * 16;

        // ---- prologue: write x_hi/x_hi/x_lo/ones columns (bytes 256-287) ----
        __syncwarp();   // previous band's ldsm reads of Z are done
        {
            float4 xv = ((const float4*)x)[row0 + cr];
            float hx = __bfloat162float(__float2bfloat16(xv.x));
            float hy = __bfloat162float(__float2bfloat16(xv.y));
            float hz = __bfloat162float(__float2bfloat16(xv.z));
            float hw_ = __bfloat162float(__float2bfloat16(xv.w));
            if ((lane & 1) == 0) {
                uint32_t p0 = packlh(xv.x, xv.y);   // rounds to x_hi
                uint32_t p1 = packlh(xv.z, xv.w);
                sts128(zrow + 256, p0, p1, p0, p1);
            } else {
                sts128(zrow + 272,
                       packlh(xv.x - hx, xv.y - hy),
                       packlh(xv.z - hz, xv.w - hw_),
                       packlh(1.0f, 1.0f), 0u);
            }
        }
        __syncwarp();

        // ---- hoist A[8]: x/ones fragment, constant across the 3 iterations ----
        uint32_t A8[4];
        ldsm4(A8, za + 256);

        // ---- 3 applications: z1 (c only), z2, z3 + y ----
        float y0 = 0.f, y1 = 0.f;
        gemm_iter<true,  false>(bb, ccb, za, zs, h2, A8, y0, y1, qc);
        __syncwarp();
        gemm_iter<false, false>(bb, ccb, za, zs, h2, A8, y0, y1, qc);
        __syncwarp();
        gemm_iter<false, true >(bb, ccb, za, zs, h2, A8, y0, y1, qc);

        // ---- reduce y across the 4 lanes sharing a row, write out ----
        y0 += __shfl_xor_sync(0xffffffffu, y0, 1);
        y0 += __shfl_xor_sync(0xffffffffu, y0, 2);
        y1 += __shfl_xor_sync(0xffffffffu, y1, 1);
        y1 += __shfl_xor_sync(0xffffffffu, y1, 2);
        if (qc == 0) {
            out[row0 + qr]     = y0 + hb0;
            out[row0 + qr + 8] = y1 + hb0;
        }
    }
}

extern "C" void kernel_launch(void* const* d_in, const int* in_sizes, int n_in,
                              void* d_out, int out_size) {
    const float* x  = (const float*)d_in[0];
    const float* Aw = (const float*)d_in[1];
    const float* Ab = (const float*)d_in[2];
    const float* Bw = (const float*)d_in[3];
    const float* Bb = (const float*)d_in[4];
    const float* hw = (const float*)d_in[5];
    const float* hb = (const float*)d_in[6];
    float* out = (float*)d_out;

    int batch  = in_sizes[0] / 4;   // x is [batch, 4]
    int nbands = batch / 16;        // 8192
    int grid   = 148;               // persistent: one CTA per SM

    cudaFuncSetAttribute(deq_mma_kernel,
                         cudaFuncAttributeMaxDynamicSharedMemorySize,
                         SM_TOTAL);
    deq_mma_kernel<<<grid, THREADS, SM_TOTAL>>>(x, Aw, Ab, Bw, Bb, hw, hb, out, nbands);
}